// round 8
// baseline (speedup 1.0000x reference)
#include <cuda_runtime.h>
#include <cuda_bf16.h>
#include <math.h>

typedef unsigned int u32;

// ---- problem constants ----
#define B_    64
#define CIN   16
#define H_    256
#define W_    256
#define COUT  64
#define OH    254
#define OW    254

// ---- implicit GEMM tiling: 128 pixels (8x16) x 64 co, K = 144 = 9 x 16 ----
#define PT_H    8
#define PT_W    16
#define MPIX    128
#define KTOT    144
#define NCHUNK  9
#define KP      168          // A row pitch in bf16 (336B: LDSM bank-conflict-free)
#define THREADS 256

// ---- smem layout (bytes) ----
#define OFF_BIASP 0                          // float2[32] bias pairs
#define OFF_HALO  256                        // fp32 [16][10][20] = 12800
#define OFF_AHI   (OFF_HALO + 12800)         // [128][168] bf16 = 43008
#define OFF_ALO   (OFF_AHI + 43008)
#define OFF_BF    (OFF_ALO + 43008)          // B fragments, 2 terms = 36864
#define SMEM_BYTES (OFF_BF + 36864)          // 135936

// B fragments in mma lane layout: [term(2)][chunk(9)][nb(8)][lane(32)][reg(2)] u32
__device__ u32 g_Bf[2 * NCHUNK * 8 * 32 * 2];

__device__ __forceinline__ u32 smem_u32(const void* p) {
    u32 a; asm("{ .reg .u64 t; cvta.to.shared.u64 t, %1; cvt.u32.u64 %0, t; }" : "=r"(a) : "l"(p));
    return a;
}

// m16n8k16 row.col f32.bf16.bf16.f32
__device__ __forceinline__ void mma16816(float c[4], const u32 a[4], u32 b0, u32 b1) {
    asm volatile(
        "mma.sync.aligned.m16n8k16.row.col.f32.bf16.bf16.f32 "
        "{%0,%1,%2,%3}, {%4,%5,%6,%7}, {%8,%9}, {%0,%1,%2,%3};"
        : "+f"(c[0]), "+f"(c[1]), "+f"(c[2]), "+f"(c[3])
        : "r"(a[0]), "r"(a[1]), "r"(a[2]), "r"(a[3]), "r"(b0), "r"(b1));
}
__device__ __forceinline__ void ldsm_x4(u32 r[4], u32 addr) {
    asm volatile("ldmatrix.sync.aligned.m8n8.x4.shared.b16 {%0,%1,%2,%3}, [%4];"
        : "=r"(r[0]), "=r"(r[1]), "=r"(r[2]), "=r"(r[3]) : "r"(addr));
}

// ============ weight prep: split + fragment-layout into g_Bf ============
__global__ void wprep_kernel(const float* __restrict__ wg) {
    int idx = blockIdx.x * blockDim.x + threadIdx.x;      // (term, c, nb, lane)
    if (idx >= 2 * NCHUNK * 8 * 32) return;
    int lane = idx & 31;
    int nb   = (idx >> 5) & 7;
    int c    = (idx >> 8) % NCHUNK;
    int term = idx / (NCHUNK * 8 * 32);
    int n = nb * 8 + (lane >> 2);
    #pragma unroll
    for (int r = 0; r < 2; r++) {
        int kbase = c * 16 + r * 8 + 2 * (lane & 3);
        u32 pack = 0;
        #pragma unroll
        for (int e = 0; e < 2; e++) {
            int k = kbase + e;
            float v = 0.0f;
            if (k < KTOT) {
                int ci = k / 9, r9 = k % 9, kh = r9 / 3, kw = r9 % 3;
                v = wg[((n * CIN + ci) * 3 + kh) * 3 + kw];
            }
            unsigned short hb;
            if (term == 0) {
                hb = __bfloat16_as_ushort(__float2bfloat16(v));
            } else {
                float hi = __bfloat162float(__float2bfloat16(v));
                hb = __bfloat16_as_ushort(__float2bfloat16(v - hi));
            }
            pack |= (u32)hb << (e * 16);
        }
        g_Bf[((size_t)((term * NCHUNK + c) * 8 + nb) * 32 + lane) * 2 + r] = pack;
    }
}

// ============ main kernel ============
__global__ __launch_bounds__(THREADS, 1)
void conv_mma_kernel(const float* __restrict__ x,
                     const float* __restrict__ bias,
                     float* __restrict__ out)
{
    extern __shared__ __align__(16) unsigned char smem[];
    const u32 sb  = smem_u32(smem);
    const int tid = threadIdx.x;
    const int wid = tid >> 5;
    const int lane = tid & 31;
    const int b   = blockIdx.z;
    const int oh0 = blockIdx.y * PT_H;
    const int ow0 = blockIdx.x * PT_W;

    // ---- copy B fragments gmem -> smem (L2-resident after first wave) ----
    {
        uint4*       d = (uint4*)(smem + OFF_BF);
        const uint4* s = (const uint4*)g_Bf;
        #pragma unroll 1
        for (int i = tid; i < 36864 / 16; i += THREADS) d[i] = s[i];
    }
    // ---- bias pairs: idx = nb*4 + j -> (co, co+1) with co = nb*8 + 2j ----
    if (tid < 32) {
        int nb = tid >> 2, j = tid & 3;
        float2 bp = make_float2(bias[nb * 8 + 2 * j], bias[nb * 8 + 2 * j + 1]);
        ((float2*)(smem + OFF_BIASP))[tid] = bp;
    }
    // ---- load x halo (fp32, zero OOB): [16][10][20] ----
    {
        float* halo = (float*)(smem + OFF_HALO);
        const float* xb = x + (size_t)b * (CIN * H_ * W_);
        #pragma unroll 1
        for (int i = tid; i < CIN * 10 * 18; i += THREADS) {
            int ci = i / 180; int rem = i - ci * 180;
            int r = rem / 18; int c = rem - r * 18;
            int gr = oh0 + r, gc = ow0 + c;
            float v = 0.0f;
            if (gr < H_ && gc < W_) v = xb[ci * (H_ * W_) + gr * W_ + gc];
            halo[(ci * 10 + r) * 20 + c] = v;
        }
    }
    __syncthreads();

    // ---- im2col A fill, hi/lo bf16 split. thread t: pixel t&127, k-half t>>7 ----
    {
        const float* halo = (const float*)(smem + OFF_HALO);
        const int p  = tid & 127;
        const int kb = (tid >> 7) * 72;
        const int pr = p >> 4, pc = p & 15;
        const float* hrow = halo + pr * 20 + pc;
        u32 ahib = sb + OFF_AHI + p * (KP * 2);
        u32 alob = sb + OFF_ALO + p * (KP * 2);
        #pragma unroll 1
        for (int pass = 0; pass < 18; pass++) {
            const int k0 = kb + pass * 4;
            float f[4];
            #pragma unroll
            for (int j = 0; j < 4; j++) {
                int k  = k0 + j;
                int ci = (k * 57) >> 9;             // k/9, exact for k<512
                int r9 = k - ci * 9;
                int kh = (r9 * 11) >> 5;            // r9/3, exact for r9<=8
                int kw = r9 - kh * 3;
                f[j] = hrow[(ci * 10 + kh) * 20 + kw];
            }
            u32 h01, h23, l01, l23;
            asm("cvt.rn.bf16x2.f32 %0, %1, %2;" : "=r"(h01) : "f"(f[1]), "f"(f[0]));
            asm("cvt.rn.bf16x2.f32 %0, %1, %2;" : "=r"(h23) : "f"(f[3]), "f"(f[2]));
            float l0 = f[0] - __uint_as_float(h01 << 16);
            float l1 = f[1] - __uint_as_float(h01 & 0xFFFF0000u);
            float l2 = f[2] - __uint_as_float(h23 << 16);
            float l3 = f[3] - __uint_as_float(h23 & 0xFFFF0000u);
            asm("cvt.rn.bf16x2.f32 %0, %1, %2;" : "=r"(l01) : "f"(l1), "f"(l0));
            asm("cvt.rn.bf16x2.f32 %0, %1, %2;" : "=r"(l23) : "f"(l3), "f"(l2));
            asm volatile("st.shared.v2.b32 [%0], {%1, %2};" :: "r"(ahib + k0 * 2), "r"(h01), "r"(h23) : "memory");
            asm volatile("st.shared.v2.b32 [%0], {%1, %2};" :: "r"(alob + k0 * 2), "r"(l01), "r"(l23) : "memory");
        }
    }
    __syncthreads();

    // ---- per-warp GEMM: 16 pixels x 64 co ----
    const int p0 = wid * 16;
    // ldmatrix lane address: matrix m = lane>>3: rows 0-7/8-15, k +0/+8
    const int arow = p0 + (lane & 7) + ((lane >> 3) & 1) * 8;
    const int acol = (lane >> 4) * 8;
    u32 aAddrHi = sb + OFF_AHI + (arow * KP + acol) * 2;
    u32 aAddrLo = sb + OFF_ALO + (arow * KP + acol) * 2;
    const unsigned char* bfp = smem + OFF_BF + lane * 8;

    float acc[8][4];
    #pragma unroll
    for (int nb = 0; nb < 8; nb++)
        #pragma unroll
        for (int r = 0; r < 4; r++) acc[nb][r] = 0.0f;

    #pragma unroll 1
    for (int c = 0; c < NCHUNK; c++) {
        u32 ah[4], al[4];
        ldsm_x4(ah, aAddrHi); aAddrHi += 32;
        ldsm_x4(al, aAddrLo); aAddrLo += 32;
        const uint2* bh = (const uint2*)(bfp + c * 2048);            // term 0
        const uint2* bl = (const uint2*)(bfp + 18432 + c * 2048);    // term 1
        #pragma unroll
        for (int nb = 0; nb < 8; nb++) {
            uint2 wh = bh[nb * 32];       // stride (32 lanes * 8B) per nb
            uint2 wl = bl[nb * 32];
            mma16816(acc[nb], ah, wh.x, wh.y);
            mma16816(acc[nb], ah, wl.x, wl.y);
            mma16816(acc[nb], al, wh.x, wh.y);
        }
    }

    // ---- epilogue: +bias, min over co (regs + 2 shuffles), tanh^2, store ----
    {
        const float2* bp = (const float2*)(smem + OFF_BIASP);
        const int j = lane & 3;
        float mA = INFINITY, mB = INFINITY;
        #pragma unroll
        for (int nb = 0; nb < 8; nb++) {
            float2 bb = bp[nb * 4 + j];
            mA = fminf(mA, fminf(acc[nb][0] + bb.x, acc[nb][1] + bb.y));
            mB = fminf(mB, fminf(acc[nb][2] + bb.x, acc[nb][3] + bb.y));
        }
        mA = fminf(mA, __shfl_xor_sync(0xFFFFFFFFu, mA, 1));
        mA = fminf(mA, __shfl_xor_sync(0xFFFFFFFFu, mA, 2));
        mB = fminf(mB, __shfl_xor_sync(0xFFFFFFFFu, mB, 1));
        mB = fminf(mB, __shfl_xor_sync(0xFFFFFFFFu, mB, 2));
        if (j == 0) {
            float* ob = out + (size_t)b * (OH * OW);
            int pA = p0 + (lane >> 2);
            int pB = pA + 8;
            int rA = oh0 + (pA >> 4), cA = ow0 + (pA & 15);
            int rB = oh0 + (pB >> 4), cB = ow0 + (pB & 15);
            if (rA < OH && cA < OW) ob[rA * OW + cA] = tanhf(tanhf(mA));
            if (rB < OH && cB < OW) ob[rB * OW + cB] = tanhf(tanhf(mB));
        }
    }
}

// ============ launch ============
extern "C" void kernel_launch(void* const* d_in, const int* in_sizes, int n_in,
                              void* d_out, int out_size)
{
    const float* x    = (const float*)d_in[0];
    const float* wg   = (const float*)d_in[1];
    const float* bias = (const float*)d_in[2];
    float* out = (float*)d_out;

    cudaFuncSetAttribute(conv_mma_kernel,
                         cudaFuncAttributeMaxDynamicSharedMemorySize, SMEM_BYTES);

    wprep_kernel<<<(2 * NCHUNK * 8 * 32 + 255) / 256, 256>>>(wg);

    dim3 grid((OW + PT_W - 1) / PT_W,    // 16
              (OH + PT_H - 1) / PT_H,    // 32
              B_);                        // 64
    conv_mma_kernel<<<grid, THREADS, SMEM_BYTES>>>(x, bias, out);
}

// round 11
// speedup vs baseline: 2.5340x; 2.5340x over previous
#include <cuda_runtime.h>
#include <cuda_bf16.h>
#include <math.h>

typedef unsigned int u32;

// ---- problem constants ----
#define B_    64
#define CIN   16
#define H_    256
#define W_    256
#define COUT  64
#define OH    254
#define OW    254

// ---- implicit GEMM tiling: 128 pixels (8x16) x 64 co, K = 144 = 9 x 16 ----
#define PT_H    8
#define PT_W    16
#define KTOT    144
#define NCHUNK  9
#define THREADS 256
#define TPC     4            // tiles per CTA (along width)

// ---- smem layout (bytes) ----
#define OFF_BIASP 0                          // float2[32] bias pairs (256 B)
#define OFF_LUT   256                        // u32[144] halo byte-offsets (576 B)
#define OFF_HALO  896                        // fp32 [16][10][20] = 12800 B
#define OFF_BF    (OFF_HALO + 12800)         // B fragments, 2 terms = 36864 B
#define SMEM_BYTES (OFF_BF + 36864)          // 50560

// B fragments in mma lane layout: [term(2)][chunk(9)][nb(8)][lane(32)][reg(2)] u32
__device__ u32 g_Bf[2 * NCHUNK * 8 * 32 * 2];

__device__ __forceinline__ u32 smem_u32(const void* p) {
    u32 a; asm("{ .reg .u64 t; cvta.to.shared.u64 t, %1; cvt.u32.u64 %0, t; }" : "=r"(a) : "l"(p));
    return a;
}
// m16n8k16 row.col f32.bf16.bf16.f32
__device__ __forceinline__ void mma16816(float c[4], const u32 a[4], u32 b0, u32 b1) {
    asm volatile(
        "mma.sync.aligned.m16n8k16.row.col.f32.bf16.bf16.f32 "
        "{%0,%1,%2,%3}, {%4,%5,%6,%7}, {%8,%9}, {%0,%1,%2,%3};"
        : "+f"(c[0]), "+f"(c[1]), "+f"(c[2]), "+f"(c[3])
        : "r"(a[0]), "r"(a[1]), "r"(a[2]), "r"(a[3]), "r"(b0), "r"(b1));
}
__device__ __forceinline__ u32 pkbf2(float hi_f, float lo_f) {
    u32 r; asm("cvt.rn.bf16x2.f32 %0, %1, %2;" : "=r"(r) : "f"(hi_f), "f"(lo_f)); return r;
}

// ============ weight prep: split + fragment-layout into g_Bf ============
__global__ void wprep_kernel(const float* __restrict__ wg) {
    int idx = blockIdx.x * blockDim.x + threadIdx.x;      // (term, c, nb, lane)
    if (idx >= 2 * NCHUNK * 8 * 32) return;
    int lane = idx & 31;
    int nb   = (idx >> 5) & 7;
    int c    = (idx >> 8) % NCHUNK;
    int term = idx / (NCHUNK * 8 * 32);
    int n = nb * 8 + (lane >> 2);
    #pragma unroll
    for (int r = 0; r < 2; r++) {
        int kbase = c * 16 + r * 8 + 2 * (lane & 3);
        u32 pack = 0;
        #pragma unroll
        for (int e = 0; e < 2; e++) {
            int k = kbase + e;
            float v = 0.0f;
            if (k < KTOT) {
                int ci = k / 9, r9 = k % 9, kh = r9 / 3, kw = r9 % 3;
                v = wg[((n * CIN + ci) * 3 + kh) * 3 + kw];
            }
            unsigned short hb;
            if (term == 0) {
                hb = __bfloat16_as_ushort(__float2bfloat16(v));
            } else {
                float hi = __bfloat162float(__float2bfloat16(v));
                hb = __bfloat16_as_ushort(__float2bfloat16(v - hi));
            }
            pack |= (u32)hb << (e * 16);
        }
        g_Bf[((size_t)((term * NCHUNK + c) * 8 + nb) * 32 + lane) * 2 + r] = pack;
    }
}

// ============ main kernel ============
__global__ __launch_bounds__(THREADS, 1)
void conv_mma_kernel(const float* __restrict__ x,
                     const float* __restrict__ bias,
                     float* __restrict__ out)
{
    extern __shared__ __align__(16) unsigned char smem[];
    const int tid  = threadIdx.x;
    const int wid  = tid >> 5;
    const int lane = tid & 31;
    const int b    = blockIdx.z;
    const int oh0  = blockIdx.y * PT_H;
    const int owg  = blockIdx.x * (PT_W * TPC);

    // ---- one-time per CTA: B fragments, bias pairs, offset LUT ----
    {
        uint4*       d = (uint4*)(smem + OFF_BF);
        const uint4* s = (const uint4*)g_Bf;
        #pragma unroll 1
        for (int i = tid; i < 36864 / 16; i += THREADS) d[i] = s[i];
    }
    if (tid < 32) {
        int nb = tid >> 2, j = tid & 3;
        ((float2*)(smem + OFF_BIASP))[tid] =
            make_float2(bias[nb * 8 + 2 * j], bias[nb * 8 + 2 * j + 1]);
    }
    if (tid < KTOT) {   // o4(k) = 4*((ci*10+kh)*20 + kw)
        int ci = tid / 9, r9 = tid % 9, kh = r9 / 3, kw = r9 % 3;
        ((u32*)(smem + OFF_LUT))[tid] = (u32)(((ci * 10 + kh) * 20 + kw) * 4);
    }

    // per-thread invariants for the GEMM stage
    const u32* lutq = (const u32*)(smem + OFF_LUT) + (lane & 3) * 2;
    const unsigned char* haloA = smem + OFF_HALO + ((wid * 20 + (lane >> 2)) << 2);
    const unsigned char* haloB8 = haloA + 32;                 // +8 pixel cols
    const unsigned char* bfp = smem + OFF_BF + lane * 8;
    const float* xb = x + (size_t)b * (CIN * H_ * W_);

    #pragma unroll 1
    for (int t = 0; t < TPC; t++) {
        const int ow0 = owg + t * PT_W;
        __syncthreads();   // previous tile done reading halo

        // ---- load x halo (fp32, zero OOB): [16][10][20] pitch 20 ----
        {
            float* halo = (float*)(smem + OFF_HALO);
            #pragma unroll 1
            for (int i = tid; i < CIN * 10 * 18; i += THREADS) {
                int ci = i / 180; int rem = i - ci * 180;
                int r = rem / 18; int c = rem - r * 18;
                int gr = oh0 + r, gc = ow0 + c;
                float v = 0.0f;
                if (gr < H_ && gc < W_) v = xb[ci * (H_ * W_) + gr * W_ + gc];
                halo[(ci * 10 + r) * 20 + c] = v;
            }
        }
        __syncthreads();

        // ---- per-warp GEMM: 16 pixels x 64 co, A frags built in regs ----
        float acc[8][4];
        #pragma unroll
        for (int nb = 0; nb < 8; nb++)
            #pragma unroll
            for (int r = 0; r < 4; r++) acc[nb][r] = 0.0f;

        #pragma unroll
        for (int c = 0; c < NCHUNK; c++) {
            u32 o0 = lutq[c * 16 + 0];
            u32 o1 = lutq[c * 16 + 1];
            u32 o8 = lutq[c * 16 + 8];
            u32 o9 = lutq[c * 16 + 9];
            float vA0 = *(const float*)(haloA + o0);
            float vA1 = *(const float*)(haloA + o1);
            float vA8 = *(const float*)(haloA + o8);
            float vA9 = *(const float*)(haloA + o9);
            float vB0 = *(const float*)(haloB8 + o0);
            float vB1 = *(const float*)(haloB8 + o1);
            float vB8 = *(const float*)(haloB8 + o8);
            float vB9 = *(const float*)(haloB8 + o9);

            u32 ah[4], al[4];
            ah[0] = pkbf2(vA1, vA0);
            ah[1] = pkbf2(vB1, vB0);
            ah[2] = pkbf2(vA9, vA8);
            ah[3] = pkbf2(vB9, vB8);
            float lA0 = vA0 - __uint_as_float(ah[0] << 16);
            float lA1 = vA1 - __uint_as_float(ah[0] & 0xFFFF0000u);
            float lB0 = vB0 - __uint_as_float(ah[1] << 16);
            float lB1 = vB1 - __uint_as_float(ah[1] & 0xFFFF0000u);
            float lA8 = vA8 - __uint_as_float(ah[2] << 16);
            float lA9 = vA9 - __uint_as_float(ah[2] & 0xFFFF0000u);
            float lB8 = vB8 - __uint_as_float(ah[3] << 16);
            float lB9 = vB9 - __uint_as_float(ah[3] & 0xFFFF0000u);
            al[0] = pkbf2(lA1, lA0);
            al[1] = pkbf2(lB1, lB0);
            al[2] = pkbf2(lA9, lA8);
            al[3] = pkbf2(lB9, lB8);

            const uint2* bh = (const uint2*)(bfp + c * 2048);           // term hi
            const uint2* bl = (const uint2*)(bfp + 18432 + c * 2048);   // term lo
            #pragma unroll
            for (int nb = 0; nb < 8; nb++) {
                uint2 wh = bh[nb * 32];
                uint2 wl = bl[nb * 32];
                mma16816(acc[nb], ah, wh.x, wh.y);
                mma16816(acc[nb], ah, wl.x, wl.y);
                mma16816(acc[nb], al, wh.x, wh.y);
            }
        }

        // ---- epilogue: +bias, min over co, tanh^2, store ----
        {
            const float2* bp = (const float2*)(smem + OFF_BIASP);
            const int j = lane & 3;
            float mA = INFINITY, mB = INFINITY;
            #pragma unroll
            for (int nb = 0; nb < 8; nb++) {
                float2 bb = bp[nb * 4 + j];
                mA = fminf(mA, fminf(acc[nb][0] + bb.x, acc[nb][1] + bb.y));
                mB = fminf(mB, fminf(acc[nb][2] + bb.x, acc[nb][3] + bb.y));
            }
            mA = fminf(mA, __shfl_xor_sync(0xFFFFFFFFu, mA, 1));
            mA = fminf(mA, __shfl_xor_sync(0xFFFFFFFFu, mA, 2));
            mB = fminf(mB, __shfl_xor_sync(0xFFFFFFFFu, mB, 1));
            mB = fminf(mB, __shfl_xor_sync(0xFFFFFFFFu, mB, 2));
            if (j == 0) {
                float* ob = out + (size_t)b * (OH * OW);
                int pA = wid * 16 + (lane >> 2);
                int pB = pA + 8;
                int rA = oh0 + (pA >> 4), cA = ow0 + (pA & 15);
                int rB = oh0 + (pB >> 4), cB = ow0 + (pB & 15);
                if (rA < OH && cA < OW) ob[rA * OW + cA] = tanhf(tanhf(mA));
                if (rB < OH && cB < OW) ob[rB * OW + cB] = tanhf(tanhf(mB));
            }
        }
    }
}

// ============ launch ============
extern "C" void kernel_launch(void* const* d_in, const int* in_sizes, int n_in,
                              void* d_out, int out_size)
{
    const float* x    = (const float*)d_in[0];
    const float* wg   = (const float*)d_in[1];
    const float* bias = (const float*)d_in[2];
    float* out = (float*)d_out;

    cudaFuncSetAttribute(conv_mma_kernel,
                         cudaFuncAttributeMaxDynamicSharedMemorySize, SMEM_BYTES);

    wprep_kernel<<<(2 * NCHUNK * 8 * 32 + 255) / 256, 256>>>(wg);

    dim3 grid((OW + PT_W * TPC - 1) / (PT_W * TPC),   // 4
              (OH + PT_H - 1) / PT_H,                 // 32
              B_);                                    // 64
    conv_mma_kernel<<<grid, THREADS, SMEM_BYTES>>>(x, bias, out);
}

// round 12
// speedup vs baseline: 3.3349x; 1.3161x over previous
#include <cuda_runtime.h>
#include <cuda_fp16.h>
#include <math.h>

typedef unsigned int u32;

// ---- problem constants ----
#define B_    64
#define CIN   16
#define H_    256
#define W_    256
#define COUT  64
#define OH    254
#define OW    254

// ---- implicit GEMM tiling: 128 pixels (8x16) x 64 co, K = 144 = 9 x 16 ----
#define PT_H    8
#define PT_W    16
#define KTOT    144
#define NCHUNK  9
#define THREADS 256
#define TPC     4            // tiles per CTA (along width)

// ---- smem layout (bytes) ----
#define OFF_BIASP 0                          // float2[32] bias pairs (256 B)
#define OFF_LUT   256                        // u32[144] halo byte-offsets (576 B)
#define OFF_HALO  896                        // fp32 [16][10][20] = 12800 B
#define OFF_BF    (OFF_HALO + 12800)         // B fragments, 2 terms = 36864 B
#define SMEM_BYTES (OFF_BF + 36864)          // 50560

// B fragments in mma lane layout: [term(2)][chunk(9)][nb(8)][lane(32)][reg(2)] u32
__device__ u32 g_Bf[2 * NCHUNK * 8 * 32 * 2];

// m16n8k16 row.col f32.f16.f16.f32
__device__ __forceinline__ void mma16816(float c[4], const u32 a[4], u32 b0, u32 b1) {
    asm volatile(
        "mma.sync.aligned.m16n8k16.row.col.f32.f16.f16.f32 "
        "{%0,%1,%2,%3}, {%4,%5,%6,%7}, {%8,%9}, {%0,%1,%2,%3};"
        : "+f"(c[0]), "+f"(c[1]), "+f"(c[2]), "+f"(c[3])
        : "r"(a[0]), "r"(a[1]), "r"(a[2]), "r"(a[3]), "r"(b0), "r"(b1));
}
__device__ __forceinline__ u32 pkhf2(float hi_f, float lo_f) {
    u32 r; asm("cvt.rn.f16x2.f32 %0, %1, %2;" : "=r"(r) : "f"(hi_f), "f"(lo_f)); return r;
}

// ============ weight prep: fp16 split + fragment-layout into g_Bf ============
__global__ void wprep_kernel(const float* __restrict__ wg) {
    int idx = blockIdx.x * blockDim.x + threadIdx.x;      // (term, c, nb, lane)
    if (idx >= 2 * NCHUNK * 8 * 32) return;
    int lane = idx & 31;
    int nb   = (idx >> 5) & 7;
    int c    = (idx >> 8) % NCHUNK;
    int term = idx / (NCHUNK * 8 * 32);
    int n = nb * 8 + (lane >> 2);
    #pragma unroll
    for (int r = 0; r < 2; r++) {
        int kbase = c * 16 + r * 8 + 2 * (lane & 3);
        u32 pack = 0;
        #pragma unroll
        for (int e = 0; e < 2; e++) {
            int k = kbase + e;
            float v = 0.0f;
            if (k < KTOT) {
                int ci = k / 9, r9 = k % 9, kh = r9 / 3, kw = r9 % 3;
                v = wg[((n * CIN + ci) * 3 + kh) * 3 + kw];
            }
            unsigned short hb;
            if (term == 0) {
                hb = __half_as_ushort(__float2half_rn(v));
            } else {
                float hi = __half2float(__float2half_rn(v));
                hb = __half_as_ushort(__float2half_rn(v - hi));
            }
            pack |= (u32)hb << (e * 16);
        }
        g_Bf[((size_t)((term * NCHUNK + c) * 8 + nb) * 32 + lane) * 2 + r] = pack;
    }
}

// ============ main kernel ============
__global__ __launch_bounds__(THREADS, 3)
void conv_mma_kernel(const float* __restrict__ x,
                     const float* __restrict__ bias,
                     float* __restrict__ out)
{
    extern __shared__ __align__(16) unsigned char smem[];
    const int tid  = threadIdx.x;
    const int wid  = tid >> 5;
    const int lane = tid & 31;
    const int b    = blockIdx.z;
    const int oh0  = blockIdx.y * PT_H;
    const int owg  = blockIdx.x * (PT_W * TPC);

    // ---- one-time per CTA: B fragments, bias pairs, offset LUT ----
    {
        uint4*       d = (uint4*)(smem + OFF_BF);
        const uint4* s = (const uint4*)g_Bf;
        #pragma unroll 1
        for (int i = tid; i < 36864 / 16; i += THREADS) d[i] = s[i];
    }
    if (tid < 32) {
        int nb = tid >> 2, j = tid & 3;
        ((float2*)(smem + OFF_BIASP))[tid] =
            make_float2(bias[nb * 8 + 2 * j], bias[nb * 8 + 2 * j + 1]);
    }
    if (tid < KTOT) {   // o4(k) = 4*((ci*10+kh)*20 + kw)
        int ci = tid / 9, r9 = tid % 9, kh = r9 / 3, kw = r9 % 3;
        ((u32*)(smem + OFF_LUT))[tid] = (u32)(((ci * 10 + kh) * 20 + kw) * 4);
    }

    // per-thread invariants for the GEMM stage
    const u32* lutq = (const u32*)(smem + OFF_LUT) + (lane & 3) * 2;
    const unsigned char* haloA  = smem + OFF_HALO + ((wid * 20 + (lane >> 2)) << 2);
    const unsigned char* haloB8 = haloA + 32;                 // +8 pixel cols
    const unsigned char* bfp = smem + OFF_BF + lane * 8;
    const float* xb = x + (size_t)b * (CIN * H_ * W_);

    #pragma unroll 1
    for (int t = 0; t < TPC; t++) {
        const int ow0 = owg + t * PT_W;
        __syncthreads();   // previous tile done reading halo

        // ---- load x halo (fp32, zero OOB): [16][10][20] pitch 20 ----
        {
            float* halo = (float*)(smem + OFF_HALO);
            #pragma unroll 1
            for (int i = tid; i < CIN * 10 * 18; i += THREADS) {
                int ci = i / 180; int rem = i - ci * 180;
                int r = rem / 18; int c = rem - r * 18;
                int gr = oh0 + r, gc = ow0 + c;
                float v = 0.0f;
                if (gr < H_ && gc < W_) v = xb[ci * (H_ * W_) + gr * W_ + gc];
                halo[(ci * 10 + r) * 20 + c] = v;
            }
        }
        __syncthreads();

        // ---- per-warp GEMM: 16 pixels x 64 co, A frags built in regs (fp16) ----
        float acc[8][4];
        #pragma unroll
        for (int nb = 0; nb < 8; nb++)
            #pragma unroll
            for (int r = 0; r < 4; r++) acc[nb][r] = 0.0f;

        #pragma unroll
        for (int c = 0; c < NCHUNK; c++) {
            u32 o0 = lutq[c * 16 + 0];
            u32 o1 = lutq[c * 16 + 1];
            u32 o8 = lutq[c * 16 + 8];
            u32 o9 = lutq[c * 16 + 9];
            float vA0 = *(const float*)(haloA + o0);
            float vA1 = *(const float*)(haloA + o1);
            float vA8 = *(const float*)(haloA + o8);
            float vA9 = *(const float*)(haloA + o9);
            float vB0 = *(const float*)(haloB8 + o0);
            float vB1 = *(const float*)(haloB8 + o1);
            float vB8 = *(const float*)(haloB8 + o8);
            float vB9 = *(const float*)(haloB8 + o9);

            u32 ah[4];
            ah[0] = pkhf2(vA1, vA0);
            ah[1] = pkhf2(vB1, vB0);
            ah[2] = pkhf2(vA9, vA8);
            ah[3] = pkhf2(vB9, vB8);

            const uint2* bh = (const uint2*)(bfp + c * 2048);           // term hi
            const uint2* bl = (const uint2*)(bfp + 18432 + c * 2048);   // term lo
            #pragma unroll
            for (int nb = 0; nb < 8; nb++) {
                uint2 wh = bh[nb * 32];
                uint2 wl = bl[nb * 32];
                mma16816(acc[nb], ah, wh.x, wh.y);
                mma16816(acc[nb], ah, wl.x, wl.y);
            }
        }

        // ---- epilogue: +bias, min over co, tanh^2, store ----
        {
            const float2* bp = (const float2*)(smem + OFF_BIASP);
            const int j = lane & 3;
            float mA = INFINITY, mB = INFINITY;
            #pragma unroll
            for (int nb = 0; nb < 8; nb++) {
                float2 bb = bp[nb * 4 + j];
                mA = fminf(mA, fminf(acc[nb][0] + bb.x, acc[nb][1] + bb.y));
                mB = fminf(mB, fminf(acc[nb][2] + bb.x, acc[nb][3] + bb.y));
            }
            mA = fminf(mA, __shfl_xor_sync(0xFFFFFFFFu, mA, 1));
            mA = fminf(mA, __shfl_xor_sync(0xFFFFFFFFu, mA, 2));
            mB = fminf(mB, __shfl_xor_sync(0xFFFFFFFFu, mB, 1));
            mB = fminf(mB, __shfl_xor_sync(0xFFFFFFFFu, mB, 2));
            if (j == 0) {
                float* ob = out + (size_t)b * (OH * OW);
                int pA = wid * 16 + (lane >> 2);
                int pB = pA + 8;
                int rA = oh0 + (pA >> 4), cA = ow0 + (pA & 15);
                int rB = oh0 + (pB >> 4), cB = ow0 + (pB & 15);
                if (rA < OH && cA < OW) ob[rA * OW + cA] = tanhf(tanhf(mA));
                if (rB < OH && cB < OW) ob[rB * OW + cB] = tanhf(tanhf(mB));
            }
        }
    }
}

// ============ launch ============
extern "C" void kernel_launch(void* const* d_in, const int* in_sizes, int n_in,
                              void* d_out, int out_size)
{
    const float* x    = (const float*)d_in[0];
    const float* wg   = (const float*)d_in[1];
    const float* bias = (const float*)d_in[2];
    float* out = (float*)d_out;

    cudaFuncSetAttribute(conv_mma_kernel,
                         cudaFuncAttributeMaxDynamicSharedMemorySize, SMEM_BYTES);

    wprep_kernel<<<(2 * NCHUNK * 8 * 32 + 255) / 256, 256>>>(wg);

    dim3 grid((OW + PT_W * TPC - 1) / (PT_W * TPC),   // 4
              (OH + PT_H - 1) / PT_H,                 // 32
              B_);                                    // 64
    conv_mma_kernel<<<grid, THREADS, SMEM_BYTES>>>(x, bias, out);
}

// round 14
// speedup vs baseline: 3.8238x; 1.1466x over previous
#include <cuda_runtime.h>
#include <cuda_fp16.h>
#include <math.h>

typedef unsigned int u32;

// ---- problem constants ----
#define B_    64
#define CIN   16
#define H_    256
#define W_    256
#define COUT  64
#define OH    254
#define OW    254

// ---- implicit GEMM tiling: 128 pixels (8x16) x 64 co, K = 144 = 9 x 16 ----
#define PT_H    8
#define PT_W    16
#define KTOT    144
#define NCHUNK  9
#define THREADS 256
#define TPC     4            // tiles per CTA (along width)

// ---- smem layout (bytes) ----
#define OFF_BIASP 0                          // float2[32] bias pairs (256 B)
#define OFF_LUT   256                        // u32[144] halo byte-offsets (576 B)
#define OFF_HALO  896                        // fp32 [16][10][20] = 12800 B
#define OFF_BF    (OFF_HALO + 12800)         // B fragments, 1 term = 18432 B
#define SMEM_BYTES (OFF_BF + 18432)          // 32128

// B fragments in mma lane layout: [chunk(9)][nb(8)][lane(32)][reg(2)] u32
__device__ u32 g_Bf[NCHUNK * 8 * 32 * 2];

// m16n8k16 row.col f32.f16.f16.f32
__device__ __forceinline__ void mma16816(float c[4], const u32 a[4], u32 b0, u32 b1) {
    asm volatile(
        "mma.sync.aligned.m16n8k16.row.col.f32.f16.f16.f32 "
        "{%0,%1,%2,%3}, {%4,%5,%6,%7}, {%8,%9}, {%0,%1,%2,%3};"
        : "+f"(c[0]), "+f"(c[1]), "+f"(c[2]), "+f"(c[3])
        : "r"(a[0]), "r"(a[1]), "r"(a[2]), "r"(a[3]), "r"(b0), "r"(b1));
}
__device__ __forceinline__ u32 pkhf2(float hi_f, float lo_f) {
    u32 r; asm("cvt.rn.f16x2.f32 %0, %1, %2;" : "=r"(r) : "f"(hi_f), "f"(lo_f)); return r;
}

// ============ weight prep: fp16 fragment-layout into g_Bf ============
__global__ void wprep_kernel(const float* __restrict__ wg) {
    int idx = blockIdx.x * blockDim.x + threadIdx.x;      // (c, nb, lane)
    if (idx >= NCHUNK * 8 * 32) return;
    int lane = idx & 31;
    int nb   = (idx >> 5) & 7;
    int c    = (idx >> 8) % NCHUNK;
    int n = nb * 8 + (lane >> 2);
    #pragma unroll
    for (int r = 0; r < 2; r++) {
        int kbase = c * 16 + r * 8 + 2 * (lane & 3);
        u32 pack = 0;
        #pragma unroll
        for (int e = 0; e < 2; e++) {
            int k = kbase + e;
            float v = 0.0f;
            if (k < KTOT) {
                int ci = k / 9, r9 = k % 9, kh = r9 / 3, kw = r9 % 3;
                v = wg[((n * CIN + ci) * 3 + kh) * 3 + kw];
            }
            pack |= (u32)__half_as_ushort(__float2half_rn(v)) << (e * 16);
        }
        g_Bf[((size_t)(c * 8 + nb) * 32 + lane) * 2 + r] = pack;
    }
}

// ============ main kernel ============
__global__ __launch_bounds__(THREADS, 3)
void conv_mma_kernel(const float* __restrict__ x,
                     const float* __restrict__ bias,
                     float* __restrict__ out)
{
    extern __shared__ __align__(16) unsigned char smem[];
    const int tid  = threadIdx.x;
    const int wid  = tid >> 5;
    const int lane = tid & 31;
    const int b    = blockIdx.z;
    const int oh0  = blockIdx.y * PT_H;
    const int owg  = blockIdx.x * (PT_W * TPC);

    // ---- one-time per CTA: B fragments, bias pairs, offset LUT ----
    {
        uint4*       d = (uint4*)(smem + OFF_BF);
        const uint4* s = (const uint4*)g_Bf;
        #pragma unroll 1
        for (int i = tid; i < 18432 / 16; i += THREADS) d[i] = s[i];
    }
    if (tid < 32) {
        int nb = tid >> 2, j = tid & 3;
        ((float2*)(smem + OFF_BIASP))[tid] =
            make_float2(bias[nb * 8 + 2 * j], bias[nb * 8 + 2 * j + 1]);
    }
    if (tid < KTOT) {   // o4(k) = 4*((ci*10+kh)*20 + kw)
        int ci = tid / 9, r9 = tid % 9, kh = r9 / 3, kw = r9 % 3;
        ((u32*)(smem + OFF_LUT))[tid] = (u32)(((ci * 10 + kh) * 20 + kw) * 4);
    }

    // per-thread invariants for the GEMM stage
    const u32* lutq = (const u32*)(smem + OFF_LUT) + (lane & 3) * 2;
    const unsigned char* haloA  = smem + OFF_HALO + ((wid * 20 + (lane >> 2)) << 2);
    const unsigned char* haloB8 = haloA + 32;                 // +8 pixel cols
    const unsigned char* bfp = smem + OFF_BF + lane * 8;
    const float* xb = x + (size_t)b * (CIN * H_ * W_);

    #pragma unroll 1
    for (int t = 0; t < TPC; t++) {
        const int ow0 = owg + t * PT_W;
        __syncthreads();   // previous tile done reading halo

        // ---- load x halo (fp32, zero OOB): [16][10][20] pitch 20 ----
        {
            float* halo = (float*)(smem + OFF_HALO);
            #pragma unroll 1
            for (int i = tid; i < CIN * 10 * 18; i += THREADS) {
                int ci = i / 180; int rem = i - ci * 180;
                int r = rem / 18; int c = rem - r * 18;
                int gr = oh0 + r, gc = ow0 + c;
                float v = 0.0f;
                if (gr < H_ && gc < W_) v = xb[ci * (H_ * W_) + gr * W_ + gc];
                halo[(ci * 10 + r) * 20 + c] = v;
            }
        }
        __syncthreads();

        // ---- per-warp GEMM: 16 pixels x 64 co, A frags built in regs (fp16) ----
        float acc[8][4];
        #pragma unroll
        for (int nb = 0; nb < 8; nb++)
            #pragma unroll
            for (int r = 0; r < 4; r++) acc[nb][r] = 0.0f;

        #pragma unroll
        for (int c = 0; c < NCHUNK; c++) {
            u32 o0 = lutq[c * 16 + 0];
            u32 o1 = lutq[c * 16 + 1];
            u32 o8 = lutq[c * 16 + 8];
            u32 o9 = lutq[c * 16 + 9];
            float vA0 = *(const float*)(haloA + o0);
            float vA1 = *(const float*)(haloA + o1);
            float vA8 = *(const float*)(haloA + o8);
            float vA9 = *(const float*)(haloA + o9);
            float vB0 = *(const float*)(haloB8 + o0);
            float vB1 = *(const float*)(haloB8 + o1);
            float vB8 = *(const float*)(haloB8 + o8);
            float vB9 = *(const float*)(haloB8 + o9);

            u32 ah[4];
            ah[0] = pkhf2(vA1, vA0);
            ah[1] = pkhf2(vB1, vB0);
            ah[2] = pkhf2(vA9, vA8);
            ah[3] = pkhf2(vB9, vB8);

            const uint2* bh = (const uint2*)(bfp + c * 2048);
            #pragma unroll
            for (int nb = 0; nb < 8; nb++) {
                uint2 wh = bh[nb * 32];
                mma16816(acc[nb], ah, wh.x, wh.y);
            }
        }

        // ---- epilogue: +bias, min over co, tanh^2, store ----
        {
            const float2* bp = (const float2*)(smem + OFF_BIASP);
            const int j = lane & 3;
            float mA = INFINITY, mB = INFINITY;
            #pragma unroll
            for (int nb = 0; nb < 8; nb++) {
                float2 bb = bp[nb * 4 + j];
                mA = fminf(mA, fminf(acc[nb][0] + bb.x, acc[nb][1] + bb.y));
                mB = fminf(mB, fminf(acc[nb][2] + bb.x, acc[nb][3] + bb.y));
            }
            mA = fminf(mA, __shfl_xor_sync(0xFFFFFFFFu, mA, 1));
            mA = fminf(mA, __shfl_xor_sync(0xFFFFFFFFu, mA, 2));
            mB = fminf(mB, __shfl_xor_sync(0xFFFFFFFFu, mB, 1));
            mB = fminf(mB, __shfl_xor_sync(0xFFFFFFFFu, mB, 2));
            if (j == 0) {
                float* ob = out + (size_t)b * (OH * OW);
                int pA = wid * 16 + (lane >> 2);
                int pB = pA + 8;
                int rA = oh0 + (pA >> 4), cA = ow0 + (pA & 15);
                int rB = oh0 + (pB >> 4), cB = ow0 + (pB & 15);
                if (rA < OH && cA < OW) ob[rA * OW + cA] = tanhf(tanhf(mA));
                if (rB < OH && cB < OW) ob[rB * OW + cB] = tanhf(tanhf(mB));
            }
        }
    }
}

// ============ launch ============
extern "C" void kernel_launch(void* const* d_in, const int* in_sizes, int n_in,
                              void* d_out, int out_size)
{
    const float* x    = (const float*)d_in[0];
    const float* wg   = (const float*)d_in[1];
    const float* bias = (const float*)d_in[2];
    float* out = (float*)d_out;

    cudaFuncSetAttribute(conv_mma_kernel,
                         cudaFuncAttributeMaxDynamicSharedMemorySize, SMEM_BYTES);

    wprep_kernel<<<(NCHUNK * 8 * 32 + 255) / 256, 256>>>(wg);

    dim3 grid((OW + PT_W * TPC - 1) / (PT_W * TPC),   // 4
              (OH + PT_H - 1) / PT_H,                 // 32
              B_);                                    // 64
    conv_mma_kernel<<<grid, THREADS, SMEM_BYTES>>>(x, bias, out);
}

// round 15
// speedup vs baseline: 4.1756x; 1.0920x over previous
#include <cuda_runtime.h>
#include <cuda_fp16.h>
#include <math.h>

typedef unsigned int u32;

// ---- problem constants ----
#define B_    64
#define CIN   16
#define H_    256
#define W_    256
#define COUT  64
#define OH    254
#define OW    254

// ---- implicit GEMM tiling: 128 pixels (8x16) x 64 co, K = 144 = 9 x 16 ----
#define PT_H    8
#define PT_W    16
#define KTOT    144
#define NCHUNK  9
#define THREADS 256
#define TPC     8            // tiles per CTA (along width)

// ---- smem layout (bytes) ----
#define OFF_BIASP 0                          // float2[32] bias pairs (256 B)
#define OFF_LUT   256                        // u32[72] packed u16 offset pairs (288 B)
#define OFF_HALO0 1024                       // fp32 [16][10][20] = 12800 B
#define OFF_HALO1 (OFF_HALO0 + 12800)
#define OFF_BF    (OFF_HALO1 + 12800)        // B fragments, 80 B/lane pitch = 23040 B
#define SMEM_BYTES (OFF_BF + 23040)          // 49664

// B fragments: u32[(c*32+lane)*20 + nb*2 + r]  (lane pitch 20 u32 = 80 B, 64 used)
__device__ u32 g_Bf[NCHUNK * 32 * 20];

// m16n8k16 row.col f32.f16.f16.f32
__device__ __forceinline__ void mma16816(float c[4], const u32 a[4], u32 b0, u32 b1) {
    asm volatile(
        "mma.sync.aligned.m16n8k16.row.col.f32.f16.f16.f32 "
        "{%0,%1,%2,%3}, {%4,%5,%6,%7}, {%8,%9}, {%0,%1,%2,%3};"
        : "+f"(c[0]), "+f"(c[1]), "+f"(c[2]), "+f"(c[3])
        : "r"(a[0]), "r"(a[1]), "r"(a[2]), "r"(a[3]), "r"(b0), "r"(b1));
}
__device__ __forceinline__ u32 pkhf2(float hi_f, float lo_f) {
    u32 r; asm("cvt.rn.f16x2.f32 %0, %1, %2;" : "=r"(r) : "f"(hi_f), "f"(lo_f)); return r;
}

// ============ weight prep: fp16 fragment-layout into g_Bf (padded pitch) ============
__global__ void wprep_kernel(const float* __restrict__ wg) {
    int idx = blockIdx.x * blockDim.x + threadIdx.x;      // (c, nb, lane)
    if (idx >= NCHUNK * 8 * 32) return;
    int lane = idx & 31;
    int nb   = (idx >> 5) & 7;
    int c    = idx >> 8;                                  // 0..8
    int n = nb * 8 + (lane >> 2);
    #pragma unroll
    for (int r = 0; r < 2; r++) {
        int kbase = c * 16 + r * 8 + 2 * (lane & 3);
        u32 pack = 0;
        #pragma unroll
        for (int e = 0; e < 2; e++) {
            int k = kbase + e;
            float v = 0.0f;
            if (k < KTOT) {
                int ci = k / 9, r9 = k % 9, kh = r9 / 3, kw = r9 % 3;
                v = wg[((n * CIN + ci) * 3 + kh) * 3 + kw];
            }
            pack |= (u32)__half_as_ushort(__float2half_rn(v)) << (e * 16);
        }
        g_Bf[(c * 32 + lane) * 20 + nb * 2 + r] = pack;
    }
}

// ============ main kernel ============
__global__ __launch_bounds__(THREADS, 3)
void conv_mma_kernel(const float* __restrict__ x,
                     const float* __restrict__ bias,
                     float* __restrict__ out)
{
    extern __shared__ __align__(16) unsigned char smem[];
    const int tid  = threadIdx.x;
    const int wid  = tid >> 5;
    const int lane = tid & 31;
    const int q    = lane & 3;
    const int b    = blockIdx.z;
    const int oh0  = blockIdx.y * PT_H;
    const int owg  = blockIdx.x * (PT_W * TPC);
    const float* xb = x + (size_t)b * (CIN * H_ * W_);

    // ---- one-time per CTA: B fragments, bias pairs, packed offset LUT, halo[0] ----
    {
        uint4*       d = (uint4*)(smem + OFF_BF);
        const uint4* s = (const uint4*)g_Bf;
        #pragma unroll 1
        for (int i = tid; i < 23040 / 16; i += THREADS) d[i] = s[i];
    }
    if (tid < 32) {
        int nb = tid >> 2, j = tid & 3;
        ((float2*)(smem + OFF_BIASP))[tid] =
            make_float2(bias[nb * 8 + 2 * j], bias[nb * 8 + 2 * j + 1]);
    }
    if (tid < 72) {   // packed offsets: e = c*8 + q*2 + half; k0 = c*16 + 2q + 8*half
        int half = tid & 1, qq = (tid >> 1) & 3, c = tid >> 3;
        int k0 = c * 16 + 2 * qq + 8 * half;
        u32 o0, o1;
        {
            int k = k0, ci = k / 9, r9 = k % 9, kh = r9 / 3, kw = r9 % 3;
            o0 = (u32)(((ci * 10 + kh) * 20 + kw) * 4);
        }
        {
            int k = k0 + 1, ci = k / 9, r9 = k % 9, kh = r9 / 3, kw = r9 % 3;
            o1 = (u32)(((ci * 10 + kh) * 20 + kw) * 4);
        }
        ((u32*)(smem + OFF_LUT))[tid] = o0 | (o1 << 16);
    }
    // halo for tile 0 into buffer 0
    {
        float* halo = (float*)(smem + OFF_HALO0);
        const int ow0 = owg;
        #pragma unroll 1
        for (int i = tid; i < CIN * 10 * 18; i += THREADS) {
            int ci = i / 180; int rem = i - ci * 180;
            int r = rem / 18; int c = rem - r * 18;
            int gr = oh0 + r, gc = ow0 + c;
            float v = 0.0f;
            if (gr < H_ && gc < W_) v = xb[ci * (H_ * W_) + gr * W_ + gc];
            halo[(ci * 10 + r) * 20 + c] = v;
        }
    }
    __syncthreads();

    // hoist packed offsets into registers (loop-invariant)
    u32 lp[NCHUNK * 2];
    {
        const u32* lut = (const u32*)(smem + OFF_LUT);
        #pragma unroll
        for (int c = 0; c < NCHUNK; c++) {
            lp[c * 2 + 0] = lut[c * 8 + q * 2 + 0];
            lp[c * 2 + 1] = lut[c * 8 + q * 2 + 1];
        }
    }
    const unsigned char* bfp = smem + OFF_BF + lane * 80;
    const u32 haloOffA = (u32)((wid * 20 + (lane >> 2)) * 4);   // pixel (row=wid, col=lane>>2)

    #pragma unroll 1
    for (int t = 0; t < TPC; t++) {
        const int ow0 = owg + t * PT_W;
        const unsigned char* haloA  = smem + ((t & 1) ? OFF_HALO1 : OFF_HALO0) + haloOffA;
        const unsigned char* haloB8 = haloA + 32;               // +8 pixel cols

        // ---- per-warp GEMM: 16 pixels x 64 co, A frags built in regs (fp16) ----
        float acc[8][4];
        #pragma unroll
        for (int nb = 0; nb < 8; nb++)
            #pragma unroll
            for (int r = 0; r < 4; r++) acc[nb][r] = 0.0f;

        #pragma unroll
        for (int c = 0; c < NCHUNK; c++) {
            u32 pk0 = lp[c * 2 + 0];          // (o(k0), o(k0+1)) bytes
            u32 pk1 = lp[c * 2 + 1];          // (o(k0+8), o(k0+9))
            u32 oA = pk0 & 0xFFFFu, oB = pk0 >> 16;
            u32 oC = pk1 & 0xFFFFu, oD = pk1 >> 16;
            float vA0 = *(const float*)(haloA  + oA);
            float vA1 = *(const float*)(haloA  + oB);
            float vA8 = *(const float*)(haloA  + oC);
            float vA9 = *(const float*)(haloA  + oD);
            float vB0 = *(const float*)(haloB8 + oA);
            float vB1 = *(const float*)(haloB8 + oB);
            float vB8 = *(const float*)(haloB8 + oC);
            float vB9 = *(const float*)(haloB8 + oD);

            u32 ah[4];
            ah[0] = pkhf2(vA1, vA0);
            ah[1] = pkhf2(vB1, vB0);
            ah[2] = pkhf2(vA9, vA8);
            ah[3] = pkhf2(vB9, vB8);

            const uint4* bq = (const uint4*)(bfp + c * 2560);
            uint4 w01 = bq[0];
            uint4 w23 = bq[1];
            uint4 w45 = bq[2];
            uint4 w67 = bq[3];
            mma16816(acc[0], ah, w01.x, w01.y);
            mma16816(acc[1], ah, w01.z, w01.w);
            mma16816(acc[2], ah, w23.x, w23.y);
            mma16816(acc[3], ah, w23.z, w23.w);
            mma16816(acc[4], ah, w45.x, w45.y);
            mma16816(acc[5], ah, w45.z, w45.w);
            mma16816(acc[6], ah, w67.x, w67.y);
            mma16816(acc[7], ah, w67.z, w67.w);
        }

        // ---- prefetch halo for tile t+1 into the other buffer (overlaps epilogue) ----
        if (t + 1 < TPC) {
            float* halo = (float*)(smem + ((t & 1) ? OFF_HALO0 : OFF_HALO1));
            const int ow1 = ow0 + PT_W;
            #pragma unroll 1
            for (int i = tid; i < CIN * 10 * 18; i += THREADS) {
                int ci = i / 180; int rem = i - ci * 180;
                int r = rem / 18; int c = rem - r * 18;
                int gr = oh0 + r, gc = ow1 + c;
                float v = 0.0f;
                if (gr < H_ && gc < W_) v = xb[ci * (H_ * W_) + gr * W_ + gc];
                halo[(ci * 10 + r) * 20 + c] = v;
            }
        }

        // ---- epilogue: +bias, min over co, tanh^2, store ----
        {
            const float2* bp = (const float2*)(smem + OFF_BIASP);
            float mA = INFINITY, mB = INFINITY;
            #pragma unroll
            for (int nb = 0; nb < 8; nb++) {
                float2 bb = bp[nb * 4 + q];
                mA = fminf(mA, fminf(acc[nb][0] + bb.x, acc[nb][1] + bb.y));
                mB = fminf(mB, fminf(acc[nb][2] + bb.x, acc[nb][3] + bb.y));
            }
            mA = fminf(mA, __shfl_xor_sync(0xFFFFFFFFu, mA, 1));
            mA = fminf(mA, __shfl_xor_sync(0xFFFFFFFFu, mA, 2));
            mB = fminf(mB, __shfl_xor_sync(0xFFFFFFFFu, mB, 1));
            mB = fminf(mB, __shfl_xor_sync(0xFFFFFFFFu, mB, 2));
            if (q == 0) {
                float* ob = out + (size_t)b * (OH * OW);
                int pA = wid * 16 + (lane >> 2);
                int pB = pA + 8;
                int rA = oh0 + (pA >> 4), cA = ow0 + (pA & 15);
                int rB = oh0 + (pB >> 4), cB = ow0 + (pB & 15);
                if (rA < OH && cA < OW) ob[rA * OW + cA] = tanhf(tanhf(mA));
                if (rB < OH && cB < OW) ob[rB * OW + cB] = tanhf(tanhf(mB));
            }
        }

        __syncthreads();   // halo[t+1] stores visible; GEMM t reads complete
    }
}

// ============ launch ============
extern "C" void kernel_launch(void* const* d_in, const int* in_sizes, int n_in,
                              void* d_out, int out_size)
{
    const float* x    = (const float*)d_in[0];
    const float* wg   = (const float*)d_in[1];
    const float* bias = (const float*)d_in[2];
    float* out = (float*)d_out;

    cudaFuncSetAttribute(conv_mma_kernel,
                         cudaFuncAttributeMaxDynamicSharedMemorySize, SMEM_BYTES);

    wprep_kernel<<<(NCHUNK * 8 * 32 + 255) / 256, 256>>>(wg);

    dim3 grid((OW + PT_W * TPC - 1) / (PT_W * TPC),   // 2
              (OH + PT_H - 1) / PT_H,                 // 32
              B_);                                    // 64
    conv_mma_kernel<<<grid, THREADS, SMEM_BYTES>>>(x, bias, out);
}